// round 14
// baseline (speedup 1.0000x reference)
#include <cuda_runtime.h>
#include <cstdint>

#define BATCH  8
#define SEQ    1024
#define DM     768
#define NHEAD  12
#define DHEAD  64
#define MTOT   (BATCH*SEQ)

// Scratch (device globals: no allocations allowed)
__device__ float g_Q[MTOT*DM];     // tf32-rounded bits
__device__ float g_K[MTOT*DM];     // tf32-rounded bits
__device__ float g_V[MTOT*DM];     // tf32-rounded bits
__device__ float g_C[MTOT*DM];     // tf32-rounded bits
__device__ float g_Wr[4*DM*DM];    // tf32-rounded Wq,Wk,Wv,Wo

// ===========================================================================
// helpers
// ===========================================================================
__device__ __forceinline__ uint32_t cvt_tf32(float f) {
    uint32_t r;
    asm("cvt.rna.tf32.f32 %0, %1;" : "=r"(r) : "f"(f));
    return r;
}

__device__ __forceinline__ void mma_tf32(float d[4], const uint32_t a[4],
                                         const uint32_t b[2]) {
    asm volatile(
        "mma.sync.aligned.m16n8k8.row.col.f32.tf32.tf32.f32 "
        "{%0,%1,%2,%3}, {%4,%5,%6,%7}, {%8,%9}, {%0,%1,%2,%3};"
        : "+f"(d[0]), "+f"(d[1]), "+f"(d[2]), "+f"(d[3])
        : "r"(a[0]), "r"(a[1]), "r"(a[2]), "r"(a[3]),
          "r"(b[0]), "r"(b[1]));
}

__device__ __forceinline__ void cp16(uint32_t saddr, const void* g) {
    asm volatile("cp.async.cg.shared.global [%0], [%1], 16;"
                 :: "r"(saddr), "l"(g));
}
#define CP_COMMIT() asm volatile("cp.async.commit_group;" ::: "memory")
#define CP_WAIT0()  asm volatile("cp.async.wait_group 0;" ::: "memory")

// ===========================================================================
// pre-round kernel (weights only): {Wq,Wk,Wv,Wo} -> g_Wr (tf32 bits)
// ===========================================================================
#define WF4 (DM*DM/4)
#define PREW_BLOCKS (4*WF4/256)

__global__ __launch_bounds__(256) void preround_w(
    const float4* __restrict__ wq, const float4* __restrict__ wk,
    const float4* __restrict__ wv, const float4* __restrict__ wo)
{
    int j = blockIdx.x * 256 + threadIdx.x;
    int wi = j / WF4;
    int off = j - wi * WF4;
    const float4* src = (wi == 0 ? wq : wi == 1 ? wk : wi == 2 ? wv : wo) + off;
    float4 v = *src;
    uint4 r;
    r.x = cvt_tf32(v.x); r.y = cvt_tf32(v.y);
    r.z = cvt_tf32(v.z); r.w = cvt_tf32(v.w);
    ((uint4*)g_Wr)[j] = r;
}

// ===========================================================================
// tf32 mma.sync GEMM (unchanged R13): Y = X @ W^T + bias
// ===========================================================================
#define ASTRIDE 20
#define BSTRIDE 20

template<bool ROUND, bool CVT_A, int NT>
__device__ __forceinline__ void gemm_mma_body(
    const float* __restrict__ X, const float* __restrict__ W,
    const float* __restrict__ bias, float* __restrict__ Y,
    int bm, int bn)
{
    __shared__ float As[128*ASTRIDE];
    __shared__ float Bs[NT*32*BSTRIDE];
    constexpr int NB4 = NT/2;

    const int t    = threadIdx.x;
    const int wid  = t >> 5;
    const int lane = t & 31;
    const int g    = lane >> 2;
    const int tig  = lane & 3;
    const int wm   = wid >> 2;
    const int wn   = wid & 3;

    const int ar = t >> 2;
    const int ac = (t & 3) * 4;
    const float* Ag = X + (size_t)(bm + ar) * DM + ac;
    const float* Bg = W + (size_t)(bn + ar) * DM + ac;

    float acc[4][NT][4];
#pragma unroll
    for (int mi = 0; mi < 4; ++mi)
#pragma unroll
        for (int ni = 0; ni < NT; ++ni)
#pragma unroll
            for (int q = 0; q < 4; ++q) acc[mi][ni][q] = 0.f;

    float4 pa[2], pb[NB4];
#pragma unroll
    for (int i = 0; i < 2; ++i) pa[i] = *(const float4*)(Ag + (size_t)i*64*DM);
#pragma unroll
    for (int i = 0; i < NB4; ++i) pb[i] = *(const float4*)(Bg + (size_t)i*64*DM);

    const uint32_t* Asu = (const uint32_t*)As;
    const uint32_t* Bsu = (const uint32_t*)Bs;

    for (int c = 0; c < 48; ++c) {
        __syncthreads();
#pragma unroll
        for (int i = 0; i < 2; ++i) {
            if (CVT_A) {
                uint4 av;
                av.x = cvt_tf32(pa[i].x); av.y = cvt_tf32(pa[i].y);
                av.z = cvt_tf32(pa[i].z); av.w = cvt_tf32(pa[i].w);
                *(uint4*)&As[(ar + i*64)*ASTRIDE + ac] = av;
            } else {
                *(float4*)&As[(ar + i*64)*ASTRIDE + ac] = pa[i];
            }
        }
#pragma unroll
        for (int i = 0; i < NB4; ++i)
            *(float4*)&Bs[(ar + i*64)*BSTRIDE + ac] = pb[i];
        __syncthreads();

        if (c + 1 < 48) {
            const float* Agc = Ag + (c + 1) * 16;
            const float* Bgc = Bg + (c + 1) * 16;
#pragma unroll
            for (int i = 0; i < 2; ++i) pa[i] = *(const float4*)(Agc + (size_t)i*64*DM);
#pragma unroll
            for (int i = 0; i < NB4; ++i) pb[i] = *(const float4*)(Bgc + (size_t)i*64*DM);
        }

#pragma unroll
        for (int kk = 0; kk < 16; kk += 8) {
            uint32_t a[4][4], b[NT][2];
#pragma unroll
            for (int mi = 0; mi < 4; ++mi) {
                const uint32_t* ap = Asu + (wm*64 + mi*16 + g)*ASTRIDE + kk + tig;
                a[mi][0] = ap[0];
                a[mi][1] = ap[8*ASTRIDE];
                a[mi][2] = ap[4];
                a[mi][3] = ap[8*ASTRIDE + 4];
            }
#pragma unroll
            for (int ni = 0; ni < NT; ++ni) {
                const uint32_t* bp = Bsu + (wn*NT*8 + ni*8 + g)*BSTRIDE + kk + tig;
                b[ni][0] = bp[0];
                b[ni][1] = bp[4];
            }
#pragma unroll
            for (int mi = 0; mi < 4; ++mi)
#pragma unroll
                for (int ni = 0; ni < NT; ++ni)
                    mma_tf32(acc[mi][ni], a[mi], b[ni]);
        }
    }

#pragma unroll
    for (int mi = 0; mi < 4; ++mi) {
        const int row0 = bm + wm*64 + mi*16 + g;
#pragma unroll
        for (int ni = 0; ni < NT; ++ni) {
            const int col = bn + wn*NT*8 + ni*8 + 2*tig;
            float2 bv = *(const float2*)(bias + col);
            float2 r0, r1;
            if (ROUND) {
                r0.x = __uint_as_float(cvt_tf32(acc[mi][ni][0] + bv.x));
                r0.y = __uint_as_float(cvt_tf32(acc[mi][ni][1] + bv.y));
                r1.x = __uint_as_float(cvt_tf32(acc[mi][ni][2] + bv.x));
                r1.y = __uint_as_float(cvt_tf32(acc[mi][ni][3] + bv.y));
            } else {
                r0.x = acc[mi][ni][0] + bv.x;
                r0.y = acc[mi][ni][1] + bv.y;
                r1.x = acc[mi][ni][2] + bv.x;
                r1.y = acc[mi][ni][3] + bv.y;
            }
            *(float2*)(Y + (size_t)row0 * DM + col)       = r0;
            *(float2*)(Y + (size_t)(row0 + 8) * DM + col) = r1;
        }
    }
}

__global__ __launch_bounds__(256) void gemm_mma_qkv(
    const float* __restrict__ X,
    const float* __restrict__ bq, const float* __restrict__ bk,
    const float* __restrict__ bv)
{
    const float* W = g_Wr + (size_t)blockIdx.z * DM * DM;
    const float* bb; float* Y;
    if (blockIdx.z == 0)      { bb = bq; Y = g_Q; }
    else if (blockIdx.z == 1) { bb = bk; Y = g_K; }
    else                      { bb = bv; Y = g_V; }
    gemm_mma_body<true, true, 8>(X, W, bb, Y, blockIdx.y * 128, blockIdx.x * 256);
}

__global__ __launch_bounds__(256, 2) void gemm_mma_one(
    const float* __restrict__ bias, float* __restrict__ Y)
{
    gemm_mma_body<false, false, 4>(g_C, g_Wr + (size_t)3 * DM * DM, bias, Y,
                                   blockIdx.y * 128, blockIdx.x * 128);
}

// ===========================================================================
// tf32 mma attention v3: 384 threads = 12 warps = 6 groups x 2 n-halves.
// Group grp owns heads {grp, grp+6}. 3 warps/SMSP for latency hiding.
// K/V regions: A = heads 0..5, B = heads 6..11 (each 32 x 384 floats).
// Strides: K 388 (=4 mod 32), V 392 (=8 mod 32) - conflict-free frag LDS.
// Same 4-sync software pipeline as R11. z: 6 group partials, no atomics.
// ===========================================================================
#define AQ_STR 772
#define SR_K 388
#define SR_V 392
#define REG_F (32*SR_V)                  // 12544 floats per region
#define RA_OFF 24704
#define RB_OFF (RA_OFF + REG_F)          // 37248
#define ZP_OFF (RB_OFF + REG_F)          // 49792
#define ZP_STR 34
#define ZP_GRP (32*ZP_STR)               // 1088
#define ATTN_SMEM_FLOATS (ZP_OFF + 6*ZP_GRP)   // 56320
#define ATTN_SMEM_BYTES (ATTN_SMEM_FLOATS*4)   // 225280

__device__ __forceinline__ void score_pass(
    const uint32_t* __restrict__ qa, const uint32_t* __restrict__ kb,
    float s[4][4])
{
#pragma unroll
    for (int kk = 0; kk < 8; ++kk) {
        uint32_t a[4];
        a[0] = qa[kk*8];
        a[1] = qa[kk*8 + 8*AQ_STR];
        a[2] = qa[kk*8 + 4];
        a[3] = qa[kk*8 + 4 + 8*AQ_STR];
#pragma unroll
        for (int j = 0; j < 4; ++j) {
            uint32_t bb[2];
            bb[0] = kb[kk*8 + j*8*SR_K];
            bb[1] = kb[kk*8 + 4 + j*8*SR_K];
            mma_tf32(s[j], a, bb);
        }
    }
}

__device__ __forceinline__ void av_pass(
    const uint32_t* __restrict__ vb, const float wp[4][4],
    const float iz0[4][2], const float iz1[4][2],
    float op[8][4], int srcA, bool odd)
{
#pragma unroll
    for (int kk = 0; kk < 4; ++kk) {
        float v0 = __shfl_sync(0xffffffffu, wp[kk][0], srcA);
        float v1 = __shfl_sync(0xffffffffu, wp[kk][1], srcA);
        float v2 = __shfl_sync(0xffffffffu, wp[kk][2], srcA);
        float v3 = __shfl_sync(0xffffffffu, wp[kk][3], srcA);
        float u0 = __shfl_sync(0xffffffffu, wp[kk][0], srcA + 2);
        float u1 = __shfl_sync(0xffffffffu, wp[kk][1], srcA + 2);
        float u2 = __shfl_sync(0xffffffffu, wp[kk][2], srcA + 2);
        float u3 = __shfl_sync(0xffffffffu, wp[kk][3], srcA + 2);
        float w00 = odd ? v1 : v0;
        float w10 = odd ? v3 : v2;
        float w01 = odd ? u1 : u0;
        float w11 = odd ? u3 : u2;
        uint32_t a[4];
        a[0] = cvt_tf32(w00 * iz0[kk][0]);
        a[1] = cvt_tf32(w10 * iz1[kk][0]);
        a[2] = cvt_tf32(w01 * iz0[kk][1]);
        a[3] = cvt_tf32(w11 * iz1[kk][1]);
#pragma unroll
        for (int j = 0; j < 8; ++j) {
            uint32_t bb[2];
            bb[0] = vb[kk*8*SR_V + j*8];
            bb[1] = vb[(kk*8+4)*SR_V + j*8];
            mma_tf32(op[j], a, bb);
        }
    }
}

__global__ __launch_bounds__(384) void attn_mma_kernel()
{
    extern __shared__ float smf[];
    float* Qs    = smf;              // [32][772]
    float* RA    = smf + RA_OFF;     // region A (heads 0..5)
    float* RB    = smf + RB_OFF;     // region B (heads 6..11)
    float* zpart = smf + ZP_OFF;     // [6][32][34]

    const int b   = blockIdx.y;
    const int n0  = blockIdx.x * 32;
    const int t   = threadIdx.x;
    const int wid = t >> 5, lane = t & 31;
    const int grp = wid >> 1, nh = wid & 1;   // grp 0..5
    const int g   = lane >> 2, tig = lane & 3;
    const int nb  = nh * 16;

    const float* Qg = g_Q + (size_t)(b*SEQ + n0)*DM;
    const float* Kg = g_K + (size_t)b*SEQ*DM;
    const float* Vg = g_V + (size_t)b*SEQ*DM;

    const uint32_t ra_base = (uint32_t)__cvta_generic_to_shared(RA);
    const uint32_t rb_base = (uint32_t)__cvta_generic_to_shared(RB);
    const uint32_t qs_base = (uint32_t)__cvta_generic_to_shared(Qs);

    // ---- stage Q once (16 f4/thread) + KA(tile 0)
    {
#pragma unroll
        for (int i = 0; i < 16; ++i) {
            int flat = t + i*384;
            int m = flat / 192;
            int c4 = flat - m*192;
            cp16(qs_base + (m*AQ_STR + c4*4)*4, Qg + (size_t)m*DM + c4*4);
        }
        CP_COMMIT();
#pragma unroll
        for (int i = 0; i < 8; ++i) {
            int flat = t + i*384;
            int m = flat / 96;
            int c4 = flat - m*96;
            cp16(ra_base + (m*SR_K + c4*4)*4, Kg + (size_t)m*DM + c4*4);
        }
        CP_COMMIT();
    }

    float o[2][8][4];
#pragma unroll
    for (int p = 0; p < 2; ++p)
#pragma unroll
        for (int j = 0; j < 8; ++j)
#pragma unroll
            for (int q = 0; q < 4; ++q) o[p][j][q] = 0.f;

    const int srcA = 4*g + (tig >> 1);
    const bool odd = (tig & 1);

    for (int m0 = 0; m0 < SEQ; m0 += 32) {
        CP_WAIT0();
        __syncthreads();   // sync1: KA visible (Q too on first iter)

        {   // stage KB (heads 6..11)
#pragma unroll
            for (int i = 0; i < 8; ++i) {
                int flat = t + i*384;
                int m = flat / 96;
                int c4 = flat - m*96;
                cp16(rb_base + (m*SR_K + c4*4)*4,
                     Kg + (size_t)(m0+m)*DM + 384 + c4*4);
            }
            CP_COMMIT();
        }

        // ---- scores(A): head grp
        float w[2][4][4];
        float wsum[4][4];
#pragma unroll
        for (int j = 0; j < 4; ++j)
#pragma unroll
            for (int q = 0; q < 4; ++q) wsum[j][q] = 0.f;

        {
            float s[4][4];
#pragma unroll
            for (int j = 0; j < 4; ++j)
#pragma unroll
                for (int q = 0; q < 4; ++q) s[j][q] = 0.f;
            score_pass((const uint32_t*)(Qs + (nb+g)*AQ_STR + grp*64 + tig),
                       (const uint32_t*)(RA + g*SR_K + grp*64 + tig), s);
#pragma unroll
            for (int j = 0; j < 4; ++j) {
                float e0 = __expf(s[j][0]*0.125f);
                float e1 = __expf(s[j][1]*0.125f);
                float e2 = __expf(s[j][2]*0.125f);
                float e3 = __expf(s[j][3]*0.125f);
                w[0][j][0]=e0; w[0][j][1]=e1; w[0][j][2]=e2; w[0][j][3]=e3;
                wsum[j][0]+=e0; wsum[j][1]+=e1; wsum[j][2]+=e2; wsum[j][3]+=e3;
            }
        }

        CP_WAIT0();
        __syncthreads();   // sync2: KB visible; A free for VA

        {   // stage VA (heads 0..5)
#pragma unroll
            for (int i = 0; i < 8; ++i) {
                int flat = t + i*384;
                int m = flat / 96;
                int c4 = flat - m*96;
                cp16(ra_base + (m*SR_V + c4*4)*4,
                     Vg + (size_t)(m0+m)*DM + c4*4);
            }
            CP_COMMIT();
        }

        // ---- scores(B): head grp+6
        {
            float s[4][4];
#pragma unroll
            for (int j = 0; j < 4; ++j)
#pragma unroll
                for (int q = 0; q < 4; ++q) s[j][q] = 0.f;
            score_pass((const uint32_t*)(Qs + (nb+g)*AQ_STR + (grp+6)*64 + tig),
                       (const uint32_t*)(RB + g*SR_K + grp*64 + tig), s);
#pragma unroll
            for (int j = 0; j < 4; ++j) {
                float e0 = __expf(s[j][0]*0.125f);
                float e1 = __expf(s[j][1]*0.125f);
                float e2 = __expf(s[j][2]*0.125f);
                float e3 = __expf(s[j][3]*0.125f);
                w[1][j][0]=e0; w[1][j][1]=e1; w[1][j][2]=e2; w[1][j][3]=e3;
                wsum[j][0]+=e0; wsum[j][1]+=e1; wsum[j][2]+=e2; wsum[j][3]+=e3;
            }
        }

        // ---- head-axis z: per-group partial sums
        {
            float* zp = zpart + grp*ZP_GRP + (nb+g)*ZP_STR + 2*tig;
#pragma unroll
            for (int j = 0; j < 4; ++j) {
                *(float2*)(zp + j*8)            = make_float2(wsum[j][0], wsum[j][1]);
                *(float2*)(zp + 8*ZP_STR + j*8) = make_float2(wsum[j][2], wsum[j][3]);
            }
        }

        CP_WAIT0();
        __syncthreads();   // sync3: VA visible; zpart complete; B free for VB

        {   // stage VB (heads 6..11)
#pragma unroll
            for (int i = 0; i < 8; ++i) {
                int flat = t + i*384;
                int m = flat / 96;
                int c4 = flat - m*96;
                cp16(rb_base + (m*SR_V + c4*4)*4,
                     Vg + (size_t)(m0+m)*DM + 384 + c4*4);
            }
            CP_COMMIT();
        }

        // invz at AV a-frag coords: sum the 6 group partials
        float iz0[4][2], iz1[4][2];
        {
            const float* zlo = zpart + (nb+g)*ZP_STR;
            const float* zhi = zpart + (nb+g+8)*ZP_STR;
#pragma unroll
            for (int kk = 0; kk < 4; ++kk) {
#pragma unroll
                for (int e = 0; e < 2; ++e) {
                    int cidx = kk*8 + tig + e*4;
                    float zl = 0.f, zh = 0.f;
#pragma unroll
                    for (int k = 0; k < 6; ++k) {
                        zl += zlo[k*ZP_GRP + cidx];
                        zh += zhi[k*ZP_GRP + cidx];
                    }
                    iz0[kk][e] = __fdividef(1.f, zl);
                    iz1[kk][e] = __fdividef(1.f, zh);
                }
            }
        }

        // ---- AV(A): head grp
        av_pass((const uint32_t*)(RA + tig*SR_V + grp*64 + g),
                w[0], iz0, iz1, o[0], srcA, odd);

        CP_WAIT0();
        __syncthreads();   // sync4: VB visible; A free for next KA

        {   // prefetch next tile's KA
            if (m0 + 32 < SEQ) {
#pragma unroll
                for (int i = 0; i < 8; ++i) {
                    int flat = t + i*384;
                    int m = flat / 96;
                    int c4 = flat - m*96;
                    cp16(ra_base + (m*SR_K + c4*4)*4,
                         Kg + (size_t)(m0+32+m)*DM + c4*4);
                }
            }
            CP_COMMIT();
        }

        // ---- AV(B): head grp+6
        av_pass((const uint32_t*)(RB + tig*SR_V + grp*64 + g),
                w[1], iz0, iz1, o[1], srcA, odd);
    }

    // ---- writeback (rounded to tf32 for the O-projection GEMM)
#pragma unroll
    for (int p = 0; p < 2; ++p) {
        const int h = grp + 6*p;
        float* Cp = g_C + (size_t)(b*SEQ + n0 + nb + g)*DM + h*64 + 2*tig;
#pragma unroll
        for (int j = 0; j < 8; ++j) {
            float2 r0, r1;
            r0.x = __uint_as_float(cvt_tf32(o[p][j][0]));
            r0.y = __uint_as_float(cvt_tf32(o[p][j][1]));
            r1.x = __uint_as_float(cvt_tf32(o[p][j][2]));
            r1.y = __uint_as_float(cvt_tf32(o[p][j][3]));
            *(float2*)(Cp + j*8)        = r0;
            *(float2*)(Cp + 8*DM + j*8) = r1;
        }
    }
}

// ===========================================================================
extern "C" void kernel_launch(void* const* d_in, const int* in_sizes, int n_in,
                              void* d_out, int out_size)
{
    const float* x  = (const float*)d_in[0];
    const float* Wq = (const float*)d_in[1];
    const float* bq = (const float*)d_in[2];
    const float* Wk = (const float*)d_in[3];
    const float* bk = (const float*)d_in[4];
    const float* Wv = (const float*)d_in[5];
    const float* bv = (const float*)d_in[6];
    const float* Wo = (const float*)d_in[7];
    const float* bo = (const float*)d_in[8];
    float* out = (float*)d_out;

    cudaFuncSetAttribute(attn_mma_kernel,
                         cudaFuncAttributeMaxDynamicSharedMemorySize,
                         ATTN_SMEM_BYTES);

    preround_w<<<PREW_BLOCKS, 256>>>(
        (const float4*)Wq, (const float4*)Wk,
        (const float4*)Wv, (const float4*)Wo);

    dim3 g3(DM/256, MTOT/128, 3);   // (3, 64, 3)
    gemm_mma_qkv<<<g3, 256>>>(x, bq, bk, bv);

    attn_mma_kernel<<<dim3(SEQ/32, BATCH), 384, ATTN_SMEM_BYTES>>>();

    dim3 gg(DM/128, MTOT/128);      // (6, 64)
    gemm_mma_one<<<gg, 256>>>(bo, out);
}

// round 15
// speedup vs baseline: 1.0397x; 1.0397x over previous
#include <cuda_runtime.h>
#include <cstdint>

#define BATCH  8
#define SEQ    1024
#define DM     768
#define NHEAD  12
#define DHEAD  64
#define MTOT   (BATCH*SEQ)

// Scratch (device globals: no allocations allowed)
__device__ float g_Q[MTOT*DM];     // tf32-rounded bits
__device__ float g_K[MTOT*DM];     // tf32-rounded bits
__device__ float g_V[MTOT*DM];     // tf32-rounded bits
__device__ float g_C[MTOT*DM];     // tf32-rounded bits
__device__ float g_Wr[4*DM*DM];    // tf32-rounded Wq,Wk,Wv,Wo

// ===========================================================================
// helpers
// ===========================================================================
__device__ __forceinline__ uint32_t cvt_tf32(float f) {
    uint32_t r;
    asm("cvt.rna.tf32.f32 %0, %1;" : "=r"(r) : "f"(f));
    return r;
}

__device__ __forceinline__ void mma_tf32(float d[4], const uint32_t a[4],
                                         const uint32_t b[2]) {
    asm volatile(
        "mma.sync.aligned.m16n8k8.row.col.f32.tf32.tf32.f32 "
        "{%0,%1,%2,%3}, {%4,%5,%6,%7}, {%8,%9}, {%0,%1,%2,%3};"
        : "+f"(d[0]), "+f"(d[1]), "+f"(d[2]), "+f"(d[3])
        : "r"(a[0]), "r"(a[1]), "r"(a[2]), "r"(a[3]),
          "r"(b[0]), "r"(b[1]));
}

__device__ __forceinline__ void cp16(uint32_t saddr, const void* g) {
    asm volatile("cp.async.cg.shared.global [%0], [%1], 16;"
                 :: "r"(saddr), "l"(g));
}
#define CP_COMMIT() asm volatile("cp.async.commit_group;" ::: "memory")
#define CP_WAIT0()  asm volatile("cp.async.wait_group 0;" ::: "memory")

// ===========================================================================
// pre-round kernel (weights only): {Wq,Wk,Wv,Wo} -> g_Wr (tf32 bits)
// ===========================================================================
#define WF4 (DM*DM/4)
#define PREW_BLOCKS (4*WF4/256)

__global__ __launch_bounds__(256) void preround_w(
    const float4* __restrict__ wq, const float4* __restrict__ wk,
    const float4* __restrict__ wv, const float4* __restrict__ wo)
{
    int j = blockIdx.x * 256 + threadIdx.x;
    int wi = j / WF4;
    int off = j - wi * WF4;
    const float4* src = (wi == 0 ? wq : wi == 1 ? wk : wi == 2 ? wv : wo) + off;
    float4 v = *src;
    uint4 r;
    r.x = cvt_tf32(v.x); r.y = cvt_tf32(v.y);
    r.z = cvt_tf32(v.z); r.w = cvt_tf32(v.w);
    ((uint4*)g_Wr)[j] = r;
}

// ===========================================================================
// tf32 mma.sync GEMM: Y[M,768] = X[M,768] @ W[768,768]^T + bias
// Block tile 128 x (NT*32), BK=16, 8 warps, warp tile 64 x (NT*8).
// Register-prefetched LDG, STS.128, scalar frag LDS.
// CVT_A: convert A to tf32 at staging; B always pre-rounded.
// ROUND: round output to tf32 bits.
// ===========================================================================
#define ASTRIDE 20
#define BSTRIDE 20

template<bool ROUND, bool CVT_A, int NT>
__device__ __forceinline__ void gemm_mma_body(
    const float* __restrict__ X, const float* __restrict__ W,
    const float* __restrict__ bias, float* __restrict__ Y,
    int bm, int bn)
{
    __shared__ float As[128*ASTRIDE];
    __shared__ float Bs[NT*32*BSTRIDE];
    constexpr int NB4 = NT/2;

    const int t    = threadIdx.x;
    const int wid  = t >> 5;
    const int lane = t & 31;
    const int g    = lane >> 2;
    const int tig  = lane & 3;
    const int wm   = wid >> 2;
    const int wn   = wid & 3;

    const int ar = t >> 2;
    const int ac = (t & 3) * 4;
    const float* Ag = X + (size_t)(bm + ar) * DM + ac;
    const float* Bg = W + (size_t)(bn + ar) * DM + ac;

    float acc[4][NT][4];
#pragma unroll
    for (int mi = 0; mi < 4; ++mi)
#pragma unroll
        for (int ni = 0; ni < NT; ++ni)
#pragma unroll
            for (int q = 0; q < 4; ++q) acc[mi][ni][q] = 0.f;

    float4 pa[2], pb[NB4];
#pragma unroll
    for (int i = 0; i < 2; ++i) pa[i] = *(const float4*)(Ag + (size_t)i*64*DM);
#pragma unroll
    for (int i = 0; i < NB4; ++i) pb[i] = *(const float4*)(Bg + (size_t)i*64*DM);

    const uint32_t* Asu = (const uint32_t*)As;
    const uint32_t* Bsu = (const uint32_t*)Bs;

    for (int c = 0; c < 48; ++c) {
        __syncthreads();
#pragma unroll
        for (int i = 0; i < 2; ++i) {
            if (CVT_A) {
                uint4 av;
                av.x = cvt_tf32(pa[i].x); av.y = cvt_tf32(pa[i].y);
                av.z = cvt_tf32(pa[i].z); av.w = cvt_tf32(pa[i].w);
                *(uint4*)&As[(ar + i*64)*ASTRIDE + ac] = av;
            } else {
                *(float4*)&As[(ar + i*64)*ASTRIDE + ac] = pa[i];
            }
        }
#pragma unroll
        for (int i = 0; i < NB4; ++i)
            *(float4*)&Bs[(ar + i*64)*BSTRIDE + ac] = pb[i];
        __syncthreads();

        if (c + 1 < 48) {
            const float* Agc = Ag + (c + 1) * 16;
            const float* Bgc = Bg + (c + 1) * 16;
#pragma unroll
            for (int i = 0; i < 2; ++i) pa[i] = *(const float4*)(Agc + (size_t)i*64*DM);
#pragma unroll
            for (int i = 0; i < NB4; ++i) pb[i] = *(const float4*)(Bgc + (size_t)i*64*DM);
        }

#pragma unroll
        for (int kk = 0; kk < 16; kk += 8) {
            uint32_t a[4][4], b[NT][2];
#pragma unroll
            for (int mi = 0; mi < 4; ++mi) {
                const uint32_t* ap = Asu + (wm*64 + mi*16 + g)*ASTRIDE + kk + tig;
                a[mi][0] = ap[0];
                a[mi][1] = ap[8*ASTRIDE];
                a[mi][2] = ap[4];
                a[mi][3] = ap[8*ASTRIDE + 4];
            }
#pragma unroll
            for (int ni = 0; ni < NT; ++ni) {
                const uint32_t* bp = Bsu + (wn*NT*8 + ni*8 + g)*BSTRIDE + kk + tig;
                b[ni][0] = bp[0];
                b[ni][1] = bp[4];
            }
#pragma unroll
            for (int mi = 0; mi < 4; ++mi)
#pragma unroll
                for (int ni = 0; ni < NT; ++ni)
                    mma_tf32(acc[mi][ni], a[mi], b[ni]);
        }
    }

#pragma unroll
    for (int mi = 0; mi < 4; ++mi) {
        const int row0 = bm + wm*64 + mi*16 + g;
#pragma unroll
        for (int ni = 0; ni < NT; ++ni) {
            const int col = bn + wn*NT*8 + ni*8 + 2*tig;
            float2 bv = *(const float2*)(bias + col);
            float2 r0, r1;
            if (ROUND) {
                r0.x = __uint_as_float(cvt_tf32(acc[mi][ni][0] + bv.x));
                r0.y = __uint_as_float(cvt_tf32(acc[mi][ni][1] + bv.y));
                r1.x = __uint_as_float(cvt_tf32(acc[mi][ni][2] + bv.x));
                r1.y = __uint_as_float(cvt_tf32(acc[mi][ni][3] + bv.y));
            } else {
                r0.x = acc[mi][ni][0] + bv.x;
                r0.y = acc[mi][ni][1] + bv.y;
                r1.x = acc[mi][ni][2] + bv.x;
                r1.y = acc[mi][ni][3] + bv.y;
            }
            *(float2*)(Y + (size_t)row0 * DM + col)       = r0;
            *(float2*)(Y + (size_t)(row0 + 8) * DM + col) = r1;
        }
    }
}

__global__ __launch_bounds__(256) void gemm_mma_qkv(
    const float* __restrict__ X,
    const float* __restrict__ bq, const float* __restrict__ bk,
    const float* __restrict__ bv)
{
    const float* W = g_Wr + (size_t)blockIdx.z * DM * DM;
    const float* bb; float* Y;
    if (blockIdx.z == 0)      { bb = bq; Y = g_Q; }
    else if (blockIdx.z == 1) { bb = bk; Y = g_K; }
    else                      { bb = bv; Y = g_V; }
    gemm_mma_body<true, true, 8>(X, W, bb, Y, blockIdx.y * 128, blockIdx.x * 256);
}

// N=192 tiles (best measured: 95.7us in R12)
__global__ __launch_bounds__(256) void gemm_mma_one(
    const float* __restrict__ bias, float* __restrict__ Y)
{
    gemm_mma_body<false, false, 6>(g_C, g_Wr + (size_t)3 * DM * DM, bias, Y,
                                   blockIdx.y * 128, blockIdx.x * 192);
}

// ===========================================================================
// tf32 mma attention (best measured config: R11/R13, 256 threads).
// softmax over HEAD axis (local per (n,m)). Q/K/V pre-rounded tf32.
// Block = (batch, 32 n-rows), 8 warps = 4 grp x 2 nh.
// K/V staged via cp.async in TWO regions: A = heads 0..7, B = heads 8..11,
// software-pipelined so staging overlaps mma. 4 syncthreads per tile.
// ===========================================================================
#define AQ_STR 772
#define SA_K 516
#define SA_V 520
#define SB_K 260
#define SB_V 264
#define RA_OFF 24704
#define RB_OFF (RA_OFF + 32*SA_V)
#define ZP_OFF (RB_OFF + 32*SB_V)
#define ZP_STR 34
#define ZP_GRP (32*ZP_STR)
#define ATTN_SMEM_FLOATS (ZP_OFF + 4*ZP_GRP)
#define ATTN_SMEM_BYTES (ATTN_SMEM_FLOATS*4)

template<int KSTR>
__device__ __forceinline__ void score_pass(
    const uint32_t* __restrict__ qa, const uint32_t* __restrict__ kb,
    float s[4][4])
{
#pragma unroll
    for (int kk = 0; kk < 8; ++kk) {
        uint32_t a[4];
        a[0] = qa[kk*8];
        a[1] = qa[kk*8 + 8*AQ_STR];
        a[2] = qa[kk*8 + 4];
        a[3] = qa[kk*8 + 4 + 8*AQ_STR];
#pragma unroll
        for (int j = 0; j < 4; ++j) {
            uint32_t bb[2];
            bb[0] = kb[kk*8 + j*8*KSTR];
            bb[1] = kb[kk*8 + 4 + j*8*KSTR];
            mma_tf32(s[j], a, bb);
        }
    }
}

template<int VSTR>
__device__ __forceinline__ void av_pass(
    const uint32_t* __restrict__ vb, const float wp[4][4],
    const float iz0[4][2], const float iz1[4][2],
    float op[8][4], int srcA, bool odd)
{
#pragma unroll
    for (int kk = 0; kk < 4; ++kk) {
        float v0 = __shfl_sync(0xffffffffu, wp[kk][0], srcA);
        float v1 = __shfl_sync(0xffffffffu, wp[kk][1], srcA);
        float v2 = __shfl_sync(0xffffffffu, wp[kk][2], srcA);
        float v3 = __shfl_sync(0xffffffffu, wp[kk][3], srcA);
        float u0 = __shfl_sync(0xffffffffu, wp[kk][0], srcA + 2);
        float u1 = __shfl_sync(0xffffffffu, wp[kk][1], srcA + 2);
        float u2 = __shfl_sync(0xffffffffu, wp[kk][2], srcA + 2);
        float u3 = __shfl_sync(0xffffffffu, wp[kk][3], srcA + 2);
        float w00 = odd ? v1 : v0;
        float w10 = odd ? v3 : v2;
        float w01 = odd ? u1 : u0;
        float w11 = odd ? u3 : u2;
        uint32_t a[4];
        a[0] = cvt_tf32(w00 * iz0[kk][0]);
        a[1] = cvt_tf32(w10 * iz1[kk][0]);
        a[2] = cvt_tf32(w01 * iz0[kk][1]);
        a[3] = cvt_tf32(w11 * iz1[kk][1]);
#pragma unroll
        for (int j = 0; j < 8; ++j) {
            uint32_t bb[2];
            bb[0] = vb[kk*8*VSTR + j*8];
            bb[1] = vb[(kk*8+4)*VSTR + j*8];
            mma_tf32(op[j], a, bb);
        }
    }
}

__global__ __launch_bounds__(256) void attn_mma_kernel()
{
    extern __shared__ float smf[];
    float* Qs    = smf;
    float* RA    = smf + RA_OFF;
    float* RB    = smf + RB_OFF;
    float* zpart = smf + ZP_OFF;

    const int b   = blockIdx.y;
    const int n0  = blockIdx.x * 32;
    const int t   = threadIdx.x;
    const int wid = t >> 5, lane = t & 31;
    const int grp = wid >> 1, nh = wid & 1;
    const int g   = lane >> 2, tig = lane & 3;
    const int nb  = nh * 16;

    const float* Qg = g_Q + (size_t)(b*SEQ + n0)*DM;
    const float* Kg = g_K + (size_t)b*SEQ*DM;
    const float* Vg = g_V + (size_t)b*SEQ*DM;

    const int srow = t >> 3;
    const int sc   = t & 7;

    const uint32_t qdst  = (uint32_t)__cvta_generic_to_shared(Qs + srow*AQ_STR + sc*4);
    const uint32_t kadst = (uint32_t)__cvta_generic_to_shared(RA + srow*SA_K + sc*4);
    const uint32_t kbdst = (uint32_t)__cvta_generic_to_shared(RB + srow*SB_K + sc*4);
    const uint32_t vadst = (uint32_t)__cvta_generic_to_shared(RA + srow*SA_V + sc*4);
    const uint32_t vbdst = (uint32_t)__cvta_generic_to_shared(RB + srow*SB_V + sc*4);

    {
        const float* qsrc = Qg + (size_t)srow * DM + sc * 4;
#pragma unroll
        for (int i = 0; i < 24; ++i)
            cp16(qdst + i*128, qsrc + i*32);
        CP_COMMIT();
        const float* ksrc = Kg + (size_t)srow * DM + sc * 4;
#pragma unroll
        for (int i = 0; i < 16; ++i)
            cp16(kadst + i*128, ksrc + i*32);
        CP_COMMIT();
    }

    float o[3][8][4];
#pragma unroll
    for (int p = 0; p < 3; ++p)
#pragma unroll
        for (int j = 0; j < 8; ++j)
#pragma unroll
            for (int q = 0; q < 4; ++q) o[p][j][q] = 0.f;

    const int srcA = 4*g + (tig >> 1);
    const bool odd = (tig & 1);

    for (int m0 = 0; m0 < SEQ; m0 += 32) {
        CP_WAIT0();
        __syncthreads();   // KA visible (Q too on first iter)

        {
            const float* ksrc = Kg + (size_t)(m0 + srow) * DM + 512 + sc * 4;
#pragma unroll
            for (int i = 0; i < 8; ++i)
                cp16(kbdst + i*128, ksrc + i*32);
            CP_COMMIT();
        }

        float w[3][4][4];
        float wsum[4][4];
#pragma unroll
        for (int j = 0; j < 4; ++j)
#pragma unroll
            for (int q = 0; q < 4; ++q) wsum[j][q] = 0.f;

#pragma unroll
        for (int p = 0; p < 2; ++p) {
            const int h = grp + 4*p;
            float s[4][4];
#pragma unroll
            for (int j = 0; j < 4; ++j)
#pragma unroll
                for (int q = 0; q < 4; ++q) s[j][q] = 0.f;
            score_pass<SA_K>(
                (const uint32_t*)(Qs + (nb+g)*AQ_STR + h*64 + tig),
                (const uint32_t*)(RA + g*SA_K + h*64 + tig), s);
#pragma unroll
            for (int j = 0; j < 4; ++j) {
                float e0 = __expf(s[j][0]*0.125f);
                float e1 = __expf(s[j][1]*0.125f);
                float e2 = __expf(s[j][2]*0.125f);
                float e3 = __expf(s[j][3]*0.125f);
                w[p][j][0]=e0; w[p][j][1]=e1; w[p][j][2]=e2; w[p][j][3]=e3;
                wsum[j][0]+=e0; wsum[j][1]+=e1; wsum[j][2]+=e2; wsum[j][3]+=e3;
            }
        }

        CP_WAIT0();
        __syncthreads();   // KB visible; A free for VA

        {
            const float* vsrc = Vg + (size_t)(m0 + srow) * DM + sc * 4;
#pragma unroll
            for (int i = 0; i < 16; ++i)
                cp16(vadst + i*128, vsrc + i*32);
            CP_COMMIT();
        }

        {
            float s[4][4];
#pragma unroll
            for (int j = 0; j < 4; ++j)
#pragma unroll
                for (int q = 0; q < 4; ++q) s[j][q] = 0.f;
            score_pass<SB_K>(
                (const uint32_t*)(Qs + (nb+g)*AQ_STR + (grp+8)*64 + tig),
                (const uint32_t*)(RB + g*SB_K + grp*64 + tig), s);
#pragma unroll
            for (int j = 0; j < 4; ++j) {
                float e0 = __expf(s[j][0]*0.125f);
                float e1 = __expf(s[j][1]*0.125f);
                float e2 = __expf(s[j][2]*0.125f);
                float e3 = __expf(s[j][3]*0.125f);
                w[2][j][0]=e0; w[2][j][1]=e1; w[2][j][2]=e2; w[2][j][3]=e3;
                wsum[j][0]+=e0; wsum[j][1]+=e1; wsum[j][2]+=e2; wsum[j][3]+=e3;
            }
        }

        {
            float* zp = zpart + grp*ZP_GRP + (nb+g)*ZP_STR + 2*tig;
#pragma unroll
            for (int j = 0; j < 4; ++j) {
                *(float2*)(zp + j*8)            = make_float2(wsum[j][0], wsum[j][1]);
                *(float2*)(zp + 8*ZP_STR + j*8) = make_float2(wsum[j][2], wsum[j][3]);
            }
        }

        CP_WAIT0();
        __syncthreads();   // VA visible; zpart complete; B free for VB

        {
            const float* vsrc = Vg + (size_t)(m0 + srow) * DM + 512 + sc * 4;
#pragma unroll
            for (int i = 0; i < 8; ++i)
                cp16(vbdst + i*128, vsrc + i*32);
            CP_COMMIT();
        }

        float iz0[4][2], iz1[4][2];
        {
            const float* zlo = zpart + (nb+g)*ZP_STR;
            const float* zhi = zpart + (nb+g+8)*ZP_STR;
#pragma unroll
            for (int kk = 0; kk < 4; ++kk) {
#pragma unroll
                for (int e = 0; e < 2; ++e) {
                    int cidx = kk*8 + tig + e*4;
                    float zl = zlo[cidx] + zlo[ZP_GRP+cidx] + zlo[2*ZP_GRP+cidx] + zlo[3*ZP_GRP+cidx];
                    float zh = zhi[cidx] + zhi[ZP_GRP+cidx] + zhi[2*ZP_GRP+cidx] + zhi[3*ZP_GRP+cidx];
                    iz0[kk][e] = __fdividef(1.f, zl);
                    iz1[kk][e] = __fdividef(1.f, zh);
                }
            }
        }

#pragma unroll
        for (int p = 0; p < 2; ++p) {
            const int h = grp + 4*p;
            av_pass<SA_V>((const uint32_t*)(RA + tig*SA_V + h*64 + g),
                          w[p], iz0, iz1, o[p], srcA, odd);
        }

        CP_WAIT0();
        __syncthreads();   // VB visible; A free for next KA

        {
            if (m0 + 32 < SEQ) {
                const float* ksrc = Kg + (size_t)(m0 + 32 + srow) * DM + sc * 4;
#pragma unroll
                for (int i = 0; i < 16; ++i)
                    cp16(kadst + i*128, ksrc + i*32);
            }
            CP_COMMIT();
        }

        av_pass<SB_V>((const uint32_t*)(RB + tig*SB_V + grp*64 + g),
                      w[2], iz0, iz1, o[2], srcA, odd);
    }

    // ---- writeback (rounded to tf32 for the O-projection GEMM)
#pragma unroll
    for (int p = 0; p < 3; ++p) {
        const int h = grp + 4*p;
        float* Cp = g_C + (size_t)(b*SEQ + n0 + nb + g)*DM + h*64 + 2*tig;
#pragma unroll
        for (int j = 0; j < 8; ++j) {
            float2 r0, r1;
            r0.x = __uint_as_float(cvt_tf32(o[p][j][0]));
            r0.y = __uint_as_float(cvt_tf32(o[p][j][1]));
            r1.x = __uint_as_float(cvt_tf32(o[p][j][2]));
            r1.y = __uint_as_float(cvt_tf32(o[p][j][3]));
            *(float2*)(Cp + j*8)        = r0;
            *(float2*)(Cp + 8*DM + j*8) = r1;
        }
    }
}

// ===========================================================================
extern "C" void kernel_launch(void* const* d_in, const int* in_sizes, int n_in,
                              void* d_out, int out_size)
{
    const float* x  = (const float*)d_in[0];
    const float* Wq = (const float*)d_in[1];
    const float* bq = (const float*)d_in[2];
    const float* Wk = (const float*)d_in[3];
    const float* bk = (const float*)d_in[4];
    const float* Wv = (const float*)d_in[5];
    const float* bv = (const float*)d_in[6];
    const float* Wo = (const float*)d_in[7];
    const float* bo = (const float*)d_in[8];
    float* out = (float*)d_out;

    cudaFuncSetAttribute(attn_mma_kernel,
                         cudaFuncAttributeMaxDynamicSharedMemorySize,
                         ATTN_SMEM_BYTES);

    preround_w<<<PREW_BLOCKS, 256>>>(
        (const float4*)Wq, (const float4*)Wk,
        (const float4*)Wv, (const float4*)Wo);

    dim3 g3(DM/256, MTOT/128, 3);   // (3, 64, 3)
    gemm_mma_qkv<<<g3, 256>>>(x, bq, bk, bv);

    attn_mma_kernel<<<dim3(SEQ/32, BATCH), 256, ATTN_SMEM_BYTES>>>();

    dim3 gg(DM/192, MTOT/128);      // (4, 64) = 256 CTAs
    gemm_mma_one<<<gg, 256>>>(bo, out);
}

// round 16
// speedup vs baseline: 1.0497x; 1.0097x over previous
#include <cuda_runtime.h>
#include <cstdint>

#define BATCH  8
#define SEQ    1024
#define DM     768
#define NHEAD  12
#define DHEAD  64
#define MTOT   (BATCH*SEQ)

// Scratch (device globals: no allocations allowed)
__device__ float g_Q[MTOT*DM];     // tf32-rounded bits
__device__ float g_K[MTOT*DM];     // tf32-rounded bits
__device__ float g_V[MTOT*DM];     // tf32-rounded bits
__device__ float g_C[MTOT*DM];     // tf32-rounded bits
__device__ float g_Xr[MTOT*DM];    // tf32-rounded x
__device__ float g_Wr[4*DM*DM];    // tf32-rounded Wq,Wk,Wv,Wo

// ===========================================================================
// helpers
// ===========================================================================
__device__ __forceinline__ uint32_t cvt_tf32(float f) {
    uint32_t r;
    asm("cvt.rna.tf32.f32 %0, %1;" : "=r"(r) : "f"(f));
    return r;
}

__device__ __forceinline__ void mma_tf32(float d[4], const uint32_t a[4],
                                         const uint32_t b[2]) {
    asm volatile(
        "mma.sync.aligned.m16n8k8.row.col.f32.tf32.tf32.f32 "
        "{%0,%1,%2,%3}, {%4,%5,%6,%7}, {%8,%9}, {%0,%1,%2,%3};"
        : "+f"(d[0]), "+f"(d[1]), "+f"(d[2]), "+f"(d[3])
        : "r"(a[0]), "r"(a[1]), "r"(a[2]), "r"(a[3]),
          "r"(b[0]), "r"(b[1]));
}

__device__ __forceinline__ void cp16(uint32_t saddr, const void* g) {
    asm volatile("cp.async.cg.shared.global [%0], [%1], 16;"
                 :: "r"(saddr), "l"(g));
}
#define CP_COMMIT() asm volatile("cp.async.commit_group;" ::: "memory")
#define CP_WAIT0()  asm volatile("cp.async.wait_group 0;" ::: "memory")

// ===========================================================================
// pre-round kernel: x -> g_Xr, {Wq,Wk,Wv,Wo} -> g_Wr (tf32 bits)
// ===========================================================================
#define XF4 (MTOT*DM/4)     // 1572864
#define WF4 (DM*DM/4)       // 147456
#define PRE_BLOCKS ((XF4 + 4*WF4) / 256)   // 8448

__global__ __launch_bounds__(256) void preround_kernel(
    const float4* __restrict__ x,
    const float4* __restrict__ wq, const float4* __restrict__ wk,
    const float4* __restrict__ wv, const float4* __restrict__ wo)
{
    int i = blockIdx.x * 256 + threadIdx.x;
    const float4* src;
    uint4* dst;
    if (i < XF4) {
        src = x + i;
        dst = (uint4*)g_Xr + i;
    } else {
        int j = i - XF4;
        int wi = j / WF4;
        int off = j - wi * WF4;
        src = (wi == 0 ? wq : wi == 1 ? wk : wi == 2 ? wv : wo) + off;
        dst = (uint4*)g_Wr + (size_t)wi * WF4 + off;
    }
    float4 v = *src;
    uint4 r;
    r.x = cvt_tf32(v.x); r.y = cvt_tf32(v.y);
    r.z = cvt_tf32(v.z); r.w = cvt_tf32(v.w);
    *dst = r;
}

// ===========================================================================
// tf32 mma.sync GEMM, BK=32 hybrid staging:
// Y[M,768] = X[M,768] @ W[768,768]^T + bias  (inputs pre-rounded tf32 bits)
// Block tile 128 x (NT*32), 8 warps, warp tile 64 x (NT*8).
// Per 32-col chunk: h0 (cols 0-15) register-prefetched LDG + STS.128;
// h1 (cols 16-31) cp.async issued before the h0 mma burst (latency hidden).
// 3 __syncthreads per 32 cols (vs 4 in the BK=16 version).
// smem stride 36 (= 4 mod 32: conflict-free fragment LDS, verified residue).
// ===========================================================================
#define ASTR2 36

template<bool ROUND, int NT>
__device__ __forceinline__ void gemm_mma_body(
    const float* __restrict__ X, const float* __restrict__ W,
    const float* __restrict__ bias, float* __restrict__ Y,
    int bm, int bn, float* __restrict__ smg)
{
    float* As = smg;                     // [128][36]
    float* Bs = smg + 128*ASTR2;         // [NT*32][36]
    constexpr int NB4 = NT/2;

    const int t    = threadIdx.x;
    const int wid  = t >> 5;
    const int lane = t & 31;
    const int g    = lane >> 2;
    const int tig  = lane & 3;
    const int wm   = wid >> 2;
    const int wn   = wid & 3;

    const int ar = t >> 2;          // 0..63
    const int ac = (t & 3) * 4;     // 0,4,8,12
    const float* Ag = X + (size_t)(bm + ar) * DM + ac;
    const float* Bg = W + (size_t)(bn + ar) * DM + ac;

    const uint32_t smb = (uint32_t)__cvta_generic_to_shared(smg);
    const uint32_t adst = smb + (ar*ASTR2 + 16 + ac) * 4;
    const uint32_t bdst = smb + (128*ASTR2 + ar*ASTR2 + 16 + ac) * 4;

    float acc[4][NT][4];
#pragma unroll
    for (int mi = 0; mi < 4; ++mi)
#pragma unroll
        for (int ni = 0; ni < NT; ++ni)
#pragma unroll
            for (int q = 0; q < 4; ++q) acc[mi][ni][q] = 0.f;

    // prefetch h0 of chunk 0
    float4 pa[2], pb[NB4];
#pragma unroll
    for (int i = 0; i < 2; ++i) pa[i] = *(const float4*)(Ag + (size_t)i*64*DM);
#pragma unroll
    for (int i = 0; i < NB4; ++i) pb[i] = *(const float4*)(Bg + (size_t)i*64*DM);

    const uint32_t* Asu = (const uint32_t*)As;
    const uint32_t* Bsu = (const uint32_t*)Bs;

    for (int c = 0; c < DM/32; ++c) {
        __syncthreads();   // sync_a: prev chunk's h1 mma complete
        // store h0 from regs
#pragma unroll
        for (int i = 0; i < 2; ++i)
            *(float4*)&As[(ar + i*64)*ASTR2 + ac] = pa[i];
#pragma unroll
        for (int i = 0; i < NB4; ++i)
            *(float4*)&Bs[(ar + i*64)*ASTR2 + ac] = pb[i];
        // issue h1 cp.async (lands in cols 16-31 while h0 mma runs)
        {
            const float* Ah1 = Ag + c*32 + 16;
            const float* Bh1 = Bg + c*32 + 16;
#pragma unroll
            for (int i = 0; i < 2; ++i)
                cp16(adst + i*64*ASTR2*4, Ah1 + (size_t)i*64*DM);
#pragma unroll
            for (int i = 0; i < NB4; ++i)
                cp16(bdst + i*64*ASTR2*4, Bh1 + (size_t)i*64*DM);
            CP_COMMIT();
        }
        __syncthreads();   // sync_b: h0 visible

        // prefetch next chunk's h0
        if (c + 1 < DM/32) {
            const float* Agc = Ag + (c + 1) * 32;
            const float* Bgc = Bg + (c + 1) * 32;
#pragma unroll
            for (int i = 0; i < 2; ++i) pa[i] = *(const float4*)(Agc + (size_t)i*64*DM);
#pragma unroll
            for (int i = 0; i < NB4; ++i) pb[i] = *(const float4*)(Bgc + (size_t)i*64*DM);
        }

        // ---- mma on h0 (kk = 0, 8)
#pragma unroll
        for (int kk = 0; kk < 16; kk += 8) {
            uint32_t a[4][4], b[NT][2];
#pragma unroll
            for (int mi = 0; mi < 4; ++mi) {
                const uint32_t* ap = Asu + (wm*64 + mi*16 + g)*ASTR2 + kk + tig;
                a[mi][0] = ap[0];
                a[mi][1] = ap[8*ASTR2];
                a[mi][2] = ap[4];
                a[mi][3] = ap[8*ASTR2 + 4];
            }
#pragma unroll
            for (int ni = 0; ni < NT; ++ni) {
                const uint32_t* bp = Bsu + (wn*NT*8 + ni*8 + g)*ASTR2 + kk + tig;
                b[ni][0] = bp[0];
                b[ni][1] = bp[4];
            }
#pragma unroll
            for (int mi = 0; mi < 4; ++mi)
#pragma unroll
                for (int ni = 0; ni < NT; ++ni)
                    mma_tf32(acc[mi][ni], a[mi], b[ni]);
        }

        CP_WAIT0();
        __syncthreads();   // sync_c: h1 visible

        // ---- mma on h1 (kk = 16, 24)
#pragma unroll
        for (int kk = 16; kk < 32; kk += 8) {
            uint32_t a[4][4], b[NT][2];
#pragma unroll
            for (int mi = 0; mi < 4; ++mi) {
                const uint32_t* ap = Asu + (wm*64 + mi*16 + g)*ASTR2 + kk + tig;
                a[mi][0] = ap[0];
                a[mi][1] = ap[8*ASTR2];
                a[mi][2] = ap[4];
                a[mi][3] = ap[8*ASTR2 + 4];
            }
#pragma unroll
            for (int ni = 0; ni < NT; ++ni) {
                const uint32_t* bp = Bsu + (wn*NT*8 + ni*8 + g)*ASTR2 + kk + tig;
                b[ni][0] = bp[0];
                b[ni][1] = bp[4];
            }
#pragma unroll
            for (int mi = 0; mi < 4; ++mi)
#pragma unroll
                for (int ni = 0; ni < NT; ++ni)
                    mma_tf32(acc[mi][ni], a[mi], b[ni]);
        }
    }

#pragma unroll
    for (int mi = 0; mi < 4; ++mi) {
        const int row0 = bm + wm*64 + mi*16 + g;
#pragma unroll
        for (int ni = 0; ni < NT; ++ni) {
            const int col = bn + wn*NT*8 + ni*8 + 2*tig;
            float2 bv = *(const float2*)(bias + col);
            float2 r0, r1;
            if (ROUND) {
                r0.x = __uint_as_float(cvt_tf32(acc[mi][ni][0] + bv.x));
                r0.y = __uint_as_float(cvt_tf32(acc[mi][ni][1] + bv.y));
                r1.x = __uint_as_float(cvt_tf32(acc[mi][ni][2] + bv.x));
                r1.y = __uint_as_float(cvt_tf32(acc[mi][ni][3] + bv.y));
            } else {
                r0.x = acc[mi][ni][0] + bv.x;
                r0.y = acc[mi][ni][1] + bv.y;
                r1.x = acc[mi][ni][2] + bv.x;
                r1.y = acc[mi][ni][3] + bv.y;
            }
            *(float2*)(Y + (size_t)row0 * DM + col)       = r0;
            *(float2*)(Y + (size_t)(row0 + 8) * DM + col) = r1;
        }
    }
}

#define QKV_SMEM_BYTES ((128 + 256)*ASTR2*4)   // 55296
#define ONE_SMEM_BYTES ((128 + 192)*ASTR2*4)   // 46080

__global__ __launch_bounds__(256) void gemm_mma_qkv(
    const float* __restrict__ bq, const float* __restrict__ bk,
    const float* __restrict__ bv)
{
    extern __shared__ float smg[];
    const float* W = g_Wr + (size_t)blockIdx.z * DM * DM;
    const float* bb; float* Y;
    if (blockIdx.z == 0)      { bb = bq; Y = g_Q; }
    else if (blockIdx.z == 1) { bb = bk; Y = g_K; }
    else                      { bb = bv; Y = g_V; }
    gemm_mma_body<true, 8>(g_Xr, W, bb, Y, blockIdx.y * 128, blockIdx.x * 256, smg);
}

__global__ __launch_bounds__(256) void gemm_mma_one(
    const float* __restrict__ bias, float* __restrict__ Y)
{
    extern __shared__ float smg[];
    gemm_mma_body<false, 6>(g_C, g_Wr + (size_t)3 * DM * DM, bias, Y,
                            blockIdx.y * 128, blockIdx.x * 192, smg);
}

// ===========================================================================
// tf32 mma attention (unchanged best config: 256 threads, A/B regions,
// software-pipelined cp.async, 4 syncthreads/tile).
// softmax over HEAD axis (local per (n,m)). Q/K/V pre-rounded tf32.
// ===========================================================================
#define AQ_STR 772
#define SA_K 516
#define SA_V 520
#define SB_K 260
#define SB_V 264
#define RA_OFF 24704
#define RB_OFF (RA_OFF + 32*SA_V)
#define ZP_OFF (RB_OFF + 32*SB_V)
#define ZP_STR 34
#define ZP_GRP (32*ZP_STR)
#define ATTN_SMEM_FLOATS (ZP_OFF + 4*ZP_GRP)
#define ATTN_SMEM_BYTES (ATTN_SMEM_FLOATS*4)

template<int KSTR>
__device__ __forceinline__ void score_pass(
    const uint32_t* __restrict__ qa, const uint32_t* __restrict__ kb,
    float s[4][4])
{
#pragma unroll
    for (int kk = 0; kk < 8; ++kk) {
        uint32_t a[4];
        a[0] = qa[kk*8];
        a[1] = qa[kk*8 + 8*AQ_STR];
        a[2] = qa[kk*8 + 4];
        a[3] = qa[kk*8 + 4 + 8*AQ_STR];
#pragma unroll
        for (int j = 0; j < 4; ++j) {
            uint32_t bb[2];
            bb[0] = kb[kk*8 + j*8*KSTR];
            bb[1] = kb[kk*8 + 4 + j*8*KSTR];
            mma_tf32(s[j], a, bb);
        }
    }
}

template<int VSTR>
__device__ __forceinline__ void av_pass(
    const uint32_t* __restrict__ vb, const float wp[4][4],
    const float iz0[4][2], const float iz1[4][2],
    float op[8][4], int srcA, bool odd)
{
#pragma unroll
    for (int kk = 0; kk < 4; ++kk) {
        float v0 = __shfl_sync(0xffffffffu, wp[kk][0], srcA);
        float v1 = __shfl_sync(0xffffffffu, wp[kk][1], srcA);
        float v2 = __shfl_sync(0xffffffffu, wp[kk][2], srcA);
        float v3 = __shfl_sync(0xffffffffu, wp[kk][3], srcA);
        float u0 = __shfl_sync(0xffffffffu, wp[kk][0], srcA + 2);
        float u1 = __shfl_sync(0xffffffffu, wp[kk][1], srcA + 2);
        float u2 = __shfl_sync(0xffffffffu, wp[kk][2], srcA + 2);
        float u3 = __shfl_sync(0xffffffffu, wp[kk][3], srcA + 2);
        float w00 = odd ? v1 : v0;
        float w10 = odd ? v3 : v2;
        float w01 = odd ? u1 : u0;
        float w11 = odd ? u3 : u2;
        uint32_t a[4];
        a[0] = cvt_tf32(w00 * iz0[kk][0]);
        a[1] = cvt_tf32(w10 * iz1[kk][0]);
        a[2] = cvt_tf32(w01 * iz0[kk][1]);
        a[3] = cvt_tf32(w11 * iz1[kk][1]);
#pragma unroll
        for (int j = 0; j < 8; ++j) {
            uint32_t bb[2];
            bb[0] = vb[kk*8*VSTR + j*8];
            bb[1] = vb[(kk*8+4)*VSTR + j*8];
            mma_tf32(op[j], a, bb);
        }
    }
}

__global__ __launch_bounds__(256) void attn_mma_kernel()
{
    extern __shared__ float smf[];
    float* Qs    = smf;
    float* RA    = smf + RA_OFF;
    float* RB    = smf + RB_OFF;
    float* zpart = smf + ZP_OFF;

    const int b   = blockIdx.y;
    const int n0  = blockIdx.x * 32;
    const int t   = threadIdx.x;
    const int wid = t >> 5, lane = t & 31;
    const int grp = wid >> 1, nh = wid & 1;
    const int g   = lane >> 2, tig = lane & 3;
    const int nb  = nh * 16;

    const float* Qg = g_Q + (size_t)(b*SEQ + n0)*DM;
    const float* Kg = g_K + (size_t)b*SEQ*DM;
    const float* Vg = g_V + (size_t)b*SEQ*DM;

    const int srow = t >> 3;
    const int sc   = t & 7;

    const uint32_t qdst  = (uint32_t)__cvta_generic_to_shared(Qs + srow*AQ_STR + sc*4);
    const uint32_t kadst = (uint32_t)__cvta_generic_to_shared(RA + srow*SA_K + sc*4);
    const uint32_t kbdst = (uint32_t)__cvta_generic_to_shared(RB + srow*SB_K + sc*4);
    const uint32_t vadst = (uint32_t)__cvta_generic_to_shared(RA + srow*SA_V + sc*4);
    const uint32_t vbdst = (uint32_t)__cvta_generic_to_shared(RB + srow*SB_V + sc*4);

    {
        const float* qsrc = Qg + (size_t)srow * DM + sc * 4;
#pragma unroll
        for (int i = 0; i < 24; ++i)
            cp16(qdst + i*128, qsrc + i*32);
        CP_COMMIT();
        const float* ksrc = Kg + (size_t)srow * DM + sc * 4;
#pragma unroll
        for (int i = 0; i < 16; ++i)
            cp16(kadst + i*128, ksrc + i*32);
        CP_COMMIT();
    }

    float o[3][8][4];
#pragma unroll
    for (int p = 0; p < 3; ++p)
#pragma unroll
        for (int j = 0; j < 8; ++j)
#pragma unroll
            for (int q = 0; q < 4; ++q) o[p][j][q] = 0.f;

    const int srcA = 4*g + (tig >> 1);
    const bool odd = (tig & 1);

    for (int m0 = 0; m0 < SEQ; m0 += 32) {
        CP_WAIT0();
        __syncthreads();   // KA visible (Q too on first iter)

        {
            const float* ksrc = Kg + (size_t)(m0 + srow) * DM + 512 + sc * 4;
#pragma unroll
            for (int i = 0; i < 8; ++i)
                cp16(kbdst + i*128, ksrc + i*32);
            CP_COMMIT();
        }

        float w[3][4][4];
        float wsum[4][4];
#pragma unroll
        for (int j = 0; j < 4; ++j)
#pragma unroll
            for (int q = 0; q < 4; ++q) wsum[j][q] = 0.f;

#pragma unroll
        for (int p = 0; p < 2; ++p) {
            const int h = grp + 4*p;
            float s[4][4];
#pragma unroll
            for (int j = 0; j < 4; ++j)
#pragma unroll
                for (int q = 0; q < 4; ++q) s[j][q] = 0.f;
            score_pass<SA_K>(
                (const uint32_t*)(Qs + (nb+g)*AQ_STR + h*64 + tig),
                (const uint32_t*)(RA + g*SA_K + h*64 + tig), s);
#pragma unroll
            for (int j = 0; j < 4; ++j) {
                float e0 = __expf(s[j][0]*0.125f);
                float e1 = __expf(s[j][1]*0.125f);
                float e2 = __expf(s[j][2]*0.125f);
                float e3 = __expf(s[j][3]*0.125f);
                w[p][j][0]=e0; w[p][j][1]=e1; w[p][j][2]=e2; w[p][j][3]=e3;
                wsum[j][0]+=e0; wsum[j][1]+=e1; wsum[j][2]+=e2; wsum[j][3]+=e3;
            }
        }

        CP_WAIT0();
        __syncthreads();   // KB visible; A free for VA

        {
            const float* vsrc = Vg + (size_t)(m0 + srow) * DM + sc * 4;
#pragma unroll
            for (int i = 0; i < 16; ++i)
                cp16(vadst + i*128, vsrc + i*32);
            CP_COMMIT();
        }

        {
            float s[4][4];
#pragma unroll
            for (int j = 0; j < 4; ++j)
#pragma unroll
                for (int q = 0; q < 4; ++q) s[j][q] = 0.f;
            score_pass<SB_K>(
                (const uint32_t*)(Qs + (nb+g)*AQ_STR + (grp+8)*64 + tig),
                (const uint32_t*)(RB + g*SB_K + grp*64 + tig), s);
#pragma unroll
            for (int j = 0; j < 4; ++j) {
                float e0 = __expf(s[j][0]*0.125f);
                float e1 = __expf(s[j][1]*0.125f);
                float e2 = __expf(s[j][2]*0.125f);
                float e3 = __expf(s[j][3]*0.125f);
                w[2][j][0]=e0; w[2][j][1]=e1; w[2][j][2]=e2; w[2][j][3]=e3;
                wsum[j][0]+=e0; wsum[j][1]+=e1; wsum[j][2]+=e2; wsum[j][3]+=e3;
            }
        }

        {
            float* zp = zpart + grp*ZP_GRP + (nb+g)*ZP_STR + 2*tig;
#pragma unroll
            for (int j = 0; j < 4; ++j) {
                *(float2*)(zp + j*8)            = make_float2(wsum[j][0], wsum[j][1]);
                *(float2*)(zp + 8*ZP_STR + j*8) = make_float2(wsum[j][2], wsum[j][3]);
            }
        }

        CP_WAIT0();
        __syncthreads();   // VA visible; zpart complete; B free for VB

        {
            const float* vsrc = Vg + (size_t)(m0 + srow) * DM + 512 + sc * 4;
#pragma unroll
            for (int i = 0; i < 8; ++i)
                cp16(vbdst + i*128, vsrc + i*32);
            CP_COMMIT();
        }

        float iz0[4][2], iz1[4][2];
        {
            const float* zlo = zpart + (nb+g)*ZP_STR;
            const float* zhi = zpart + (nb+g+8)*ZP_STR;
#pragma unroll
            for (int kk = 0; kk < 4; ++kk) {
#pragma unroll
                for (int e = 0; e < 2; ++e) {
                    int cidx = kk*8 + tig + e*4;
                    float zl = zlo[cidx] + zlo[ZP_GRP+cidx] + zlo[2*ZP_GRP+cidx] + zlo[3*ZP_GRP+cidx];
                    float zh = zhi[cidx] + zhi[ZP_GRP+cidx] + zhi[2*ZP_GRP+cidx] + zhi[3*ZP_GRP+cidx];
                    iz0[kk][e] = __fdividef(1.f, zl);
                    iz1[kk][e] = __fdividef(1.f, zh);
                }
            }
        }

#pragma unroll
        for (int p = 0; p < 2; ++p) {
            const int h = grp + 4*p;
            av_pass<SA_V>((const uint32_t*)(RA + tig*SA_V + h*64 + g),
                          w[p], iz0, iz1, o[p], srcA, odd);
        }

        CP_WAIT0();
        __syncthreads();   // VB visible; A free for next KA

        {
            if (m0 + 32 < SEQ) {
                const float* ksrc = Kg + (size_t)(m0 + 32 + srow) * DM + sc * 4;
#pragma unroll
                for (int i = 0; i < 16; ++i)
                    cp16(kadst + i*128, ksrc + i*32);
            }
            CP_COMMIT();
        }

        av_pass<SB_V>((const uint32_t*)(RB + tig*SB_V + grp*64 + g),
                      w[2], iz0, iz1, o[2], srcA, odd);
    }

    // ---- writeback (rounded to tf32 for the O-projection GEMM)
#pragma unroll
    for (int p = 0; p < 3; ++p) {
        const int h = grp + 4*p;
        float* Cp = g_C + (size_t)(b*SEQ + n0 + nb + g)*DM + h*64 + 2*tig;
#pragma unroll
        for (int j = 0; j < 8; ++j) {
            float2 r0, r1;
            r0.x = __uint_as_float(cvt_tf32(o[p][j][0]));
            r0.y = __uint_as_float(cvt_tf32(o[p][j][1]));
            r1.x = __uint_as_float(cvt_tf32(o[p][j][2]));
            r1.y = __uint_as_float(cvt_tf32(o[p][j][3]));
            *(float2*)(Cp + j*8)        = r0;
            *(float2*)(Cp + 8*DM + j*8) = r1;
        }
    }
}

// ===========================================================================
extern "C" void kernel_launch(void* const* d_in, const int* in_sizes, int n_in,
                              void* d_out, int out_size)
{
    const float* x  = (const float*)d_in[0];
    const float* Wq = (const float*)d_in[1];
    const float* bq = (const float*)d_in[2];
    const float* Wk = (const float*)d_in[3];
    const float* bk = (const float*)d_in[4];
    const float* Wv = (const float*)d_in[5];
    const float* bv = (const float*)d_in[6];
    const float* Wo = (const float*)d_in[7];
    const float* bo = (const float*)d_in[8];
    float* out = (float*)d_out;

    cudaFuncSetAttribute(attn_mma_kernel,
                         cudaFuncAttributeMaxDynamicSharedMemorySize,
                         ATTN_SMEM_BYTES);
    cudaFuncSetAttribute(gemm_mma_qkv,
                         cudaFuncAttributeMaxDynamicSharedMemorySize,
                         QKV_SMEM_BYTES);
    cudaFuncSetAttribute(gemm_mma_one,
                         cudaFuncAttributeMaxDynamicSharedMemorySize,
                         ONE_SMEM_BYTES);

    preround_kernel<<<PRE_BLOCKS, 256>>>(
        (const float4*)x, (const float4*)Wq, (const float4*)Wk,
        (const float4*)Wv, (const float4*)Wo);

    dim3 g3(DM/256, MTOT/128, 3);   // (3, 64, 3)
    gemm_mma_qkv<<<g3, 256, QKV_SMEM_BYTES>>>(bq, bk, bv);

    attn_mma_kernel<<<dim3(SEQ/32, BATCH), 256, ATTN_SMEM_BYTES>>>();

    dim3 gg(DM/192, MTOT/128);      // (4, 64) = 256 CTAs
    gemm_mma_one<<<gg, 256, ONE_SMEM_BYTES>>>(bo, out);
}

// round 17
// speedup vs baseline: 1.0648x; 1.0144x over previous
#include <cuda_runtime.h>
#include <cstdint>

#define BATCH  8
#define SEQ    1024
#define DM     768
#define NHEAD  12
#define DHEAD  64
#define MTOT   (BATCH*SEQ)

// Scratch (device globals: no allocations allowed)
__device__ float g_Q[MTOT*DM];     // tf32-rounded bits
__device__ float g_K[MTOT*DM];     // tf32-rounded bits
__device__ float g_V[MTOT*DM];     // tf32-rounded bits
__device__ float g_C[MTOT*DM];     // tf32-rounded bits
__device__ float g_Xr[MTOT*DM];    // tf32-rounded x
__device__ float g_Wr[4*DM*DM];    // tf32-rounded Wq,Wk,Wv,Wo

// ===========================================================================
// helpers
// ===========================================================================
__device__ __forceinline__ uint32_t cvt_tf32(float f) {
    uint32_t r;
    asm("cvt.rna.tf32.f32 %0, %1;" : "=r"(r) : "f"(f));
    return r;
}

__device__ __forceinline__ void mma_tf32(float d[4], const uint32_t a[4],
                                         const uint32_t b[2]) {
    asm volatile(
        "mma.sync.aligned.m16n8k8.row.col.f32.tf32.tf32.f32 "
        "{%0,%1,%2,%3}, {%4,%5,%6,%7}, {%8,%9}, {%0,%1,%2,%3};"
        : "+f"(d[0]), "+f"(d[1]), "+f"(d[2]), "+f"(d[3])
        : "r"(a[0]), "r"(a[1]), "r"(a[2]), "r"(a[3]),
          "r"(b[0]), "r"(b[1]));
}

__device__ __forceinline__ void cp16(uint32_t saddr, const void* g) {
    asm volatile("cp.async.cg.shared.global [%0], [%1], 16;"
                 :: "r"(saddr), "l"(g));
}
#define CP_COMMIT() asm volatile("cp.async.commit_group;" ::: "memory")
#define CP_WAIT0()  asm volatile("cp.async.wait_group 0;" ::: "memory")

// ===========================================================================
// pre-round kernel: x -> g_Xr, {Wq,Wk,Wv,Wo} -> g_Wr (tf32 bits)
// ===========================================================================
#define XF4 (MTOT*DM/4)     // 1572864
#define WF4 (DM*DM/4)       // 147456
#define PRE_BLOCKS ((XF4 + 4*WF4) / 256)   // 8448

__global__ __launch_bounds__(256) void preround_kernel(
    const float4* __restrict__ x,
    const float4* __restrict__ wq, const float4* __restrict__ wk,
    const float4* __restrict__ wv, const float4* __restrict__ wo)
{
    int i = blockIdx.x * 256 + threadIdx.x;
    const float4* src;
    uint4* dst;
    if (i < XF4) {
        src = x + i;
        dst = (uint4*)g_Xr + i;
    } else {
        int j = i - XF4;
        int wi = j / WF4;
        int off = j - wi * WF4;
        src = (wi == 0 ? wq : wi == 1 ? wk : wi == 2 ? wv : wo) + off;
        dst = (uint4*)g_Wr + (size_t)wi * WF4 + off;
    }
    float4 v = *src;
    uint4 r;
    r.x = cvt_tf32(v.x); r.y = cvt_tf32(v.y);
    r.z = cvt_tf32(v.z); r.w = cvt_tf32(v.w);
    *dst = r;
}

// ===========================================================================
// tf32 mma.sync GEMM, BK=32 hybrid staging v2:
// Y[M,768] = X[M,768] @ W[768,768]^T + bias  (inputs pre-rounded tf32 bits)
// Block tile 128 x (NT*32), 8 warps, warp tile 64 x (NT*8).
// Per 32-col chunk: A h0+h1 and B h0 register-prefetched (STS.128);
// B h1 cp.async issued before the h0 mma burst (latency hidden).
// 3 __syncthreads per 32 cols. smem stride 36 (=4 mod 32, conflict-free).
// ===========================================================================
#define ASTR2 36

template<bool ROUND, int NT>
__device__ __forceinline__ void gemm_mma_body(
    const float* __restrict__ X, const float* __restrict__ W,
    const float* __restrict__ bias, float* __restrict__ Y,
    int bm, int bn, float* __restrict__ smg)
{
    float* As = smg;                     // [128][36]
    float* Bs = smg + 128*ASTR2;         // [NT*32][36]
    constexpr int NB4 = NT/2;

    const int t    = threadIdx.x;
    const int wid  = t >> 5;
    const int lane = t & 31;
    const int g    = lane >> 2;
    const int tig  = lane & 3;
    const int wm   = wid >> 2;
    const int wn   = wid & 3;

    const int ar = t >> 2;          // 0..63
    const int ac = (t & 3) * 4;     // 0,4,8,12
    const float* Ag = X + (size_t)(bm + ar) * DM + ac;
    const float* Bg = W + (size_t)(bn + ar) * DM + ac;

    const uint32_t smb = (uint32_t)__cvta_generic_to_shared(smg);
    const uint32_t bdst = smb + (128*ASTR2 + ar*ASTR2 + 16 + ac) * 4;

    float acc[4][NT][4];
#pragma unroll
    for (int mi = 0; mi < 4; ++mi)
#pragma unroll
        for (int ni = 0; ni < NT; ++ni)
#pragma unroll
            for (int q = 0; q < 4; ++q) acc[mi][ni][q] = 0.f;

    // prefetch chunk 0: A h0+h1, B h0
    float4 pa[4], pb[NB4];
#pragma unroll
    for (int i = 0; i < 2; ++i) {
        pa[i]   = *(const float4*)(Ag + (size_t)i*64*DM);
        pa[i+2] = *(const float4*)(Ag + (size_t)i*64*DM + 16);
    }
#pragma unroll
    for (int i = 0; i < NB4; ++i) pb[i] = *(const float4*)(Bg + (size_t)i*64*DM);

    const uint32_t* Asu = (const uint32_t*)As;
    const uint32_t* Bsu = (const uint32_t*)Bs;

    for (int c = 0; c < DM/32; ++c) {
        __syncthreads();   // sync_a: prev chunk's h1 mma complete
        // store A h0+h1 and B h0 from regs
#pragma unroll
        for (int i = 0; i < 2; ++i) {
            *(float4*)&As[(ar + i*64)*ASTR2 + ac]      = pa[i];
            *(float4*)&As[(ar + i*64)*ASTR2 + 16 + ac] = pa[i+2];
        }
#pragma unroll
        for (int i = 0; i < NB4; ++i)
            *(float4*)&Bs[(ar + i*64)*ASTR2 + ac] = pb[i];
        // issue B h1 cp.async (lands in cols 16-31 while h0 mma runs)
        {
            const float* Bh1 = Bg + c*32 + 16;
#pragma unroll
            for (int i = 0; i < NB4; ++i)
                cp16(bdst + i*64*ASTR2*4, Bh1 + (size_t)i*64*DM);
            CP_COMMIT();
        }
        __syncthreads();   // sync_b: h0 (and A h1) visible

        // prefetch next chunk's A h0+h1 and B h0
        if (c + 1 < DM/32) {
            const float* Agc = Ag + (c + 1) * 32;
            const float* Bgc = Bg + (c + 1) * 32;
#pragma unroll
            for (int i = 0; i < 2; ++i) {
                pa[i]   = *(const float4*)(Agc + (size_t)i*64*DM);
                pa[i+2] = *(const float4*)(Agc + (size_t)i*64*DM + 16);
            }
#pragma unroll
            for (int i = 0; i < NB4; ++i) pb[i] = *(const float4*)(Bgc + (size_t)i*64*DM);
        }

        // ---- mma on h0 (kk = 0, 8)
#pragma unroll
        for (int kk = 0; kk < 16; kk += 8) {
            uint32_t a[4][4], b[NT][2];
#pragma unroll
            for (int mi = 0; mi < 4; ++mi) {
                const uint32_t* ap = Asu + (wm*64 + mi*16 + g)*ASTR2 + kk + tig;
                a[mi][0] = ap[0];
                a[mi][1] = ap[8*ASTR2];
                a[mi][2] = ap[4];
                a[mi][3] = ap[8*ASTR2 + 4];
            }
#pragma unroll
            for (int ni = 0; ni < NT; ++ni) {
                const uint32_t* bp = Bsu + (wn*NT*8 + ni*8 + g)*ASTR2 + kk + tig;
                b[ni][0] = bp[0];
                b[ni][1] = bp[4];
            }
#pragma unroll
            for (int mi = 0; mi < 4; ++mi)
#pragma unroll
                for (int ni = 0; ni < NT; ++ni)
                    mma_tf32(acc[mi][ni], a[mi], b[ni]);
        }

        CP_WAIT0();
        __syncthreads();   // sync_c: B h1 visible

        // ---- mma on h1 (kk = 16, 24)
#pragma unroll
        for (int kk = 16; kk < 32; kk += 8) {
            uint32_t a[4][4], b[NT][2];
#pragma unroll
            for (int mi = 0; mi < 4; ++mi) {
                const uint32_t* ap = Asu + (wm*64 + mi*16 + g)*ASTR2 + kk + tig;
                a[mi][0] = ap[0];
                a[mi][1] = ap[8*ASTR2];
                a[mi][2] = ap[4];
                a[mi][3] = ap[8*ASTR2 + 4];
            }
#pragma unroll
            for (int ni = 0; ni < NT; ++ni) {
                const uint32_t* bp = Bsu + (wn*NT*8 + ni*8 + g)*ASTR2 + kk + tig;
                b[ni][0] = bp[0];
                b[ni][1] = bp[4];
            }
#pragma unroll
            for (int mi = 0; mi < 4; ++mi)
#pragma unroll
                for (int ni = 0; ni < NT; ++ni)
                    mma_tf32(acc[mi][ni], a[mi], b[ni]);
        }
    }

#pragma unroll
    for (int mi = 0; mi < 4; ++mi) {
        const int row0 = bm + wm*64 + mi*16 + g;
#pragma unroll
        for (int ni = 0; ni < NT; ++ni) {
            const int col = bn + wn*NT*8 + ni*8 + 2*tig;
            float2 bv = *(const float2*)(bias + col);
            float2 r0, r1;
            if (ROUND) {
                r0.x = __uint_as_float(cvt_tf32(acc[mi][ni][0] + bv.x));
                r0.y = __uint_as_float(cvt_tf32(acc[mi][ni][1] + bv.y));
                r1.x = __uint_as_float(cvt_tf32(acc[mi][ni][2] + bv.x));
                r1.y = __uint_as_float(cvt_tf32(acc[mi][ni][3] + bv.y));
            } else {
                r0.x = acc[mi][ni][0] + bv.x;
                r0.y = acc[mi][ni][1] + bv.y;
                r1.x = acc[mi][ni][2] + bv.x;
                r1.y = acc[mi][ni][3] + bv.y;
            }
            *(float2*)(Y + (size_t)row0 * DM + col)       = r0;
            *(float2*)(Y + (size_t)(row0 + 8) * DM + col) = r1;
        }
    }
}

#define QKV_SMEM_BYTES ((128 + 256)*ASTR2*4)   // 55296
#define ONE_SMEM_BYTES ((128 + 192)*ASTR2*4)   // 46080

__global__ __launch_bounds__(256) void gemm_mma_qkv(
    const float* __restrict__ bq, const float* __restrict__ bk,
    const float* __restrict__ bv)
{
    extern __shared__ float smg[];
    const float* W = g_Wr + (size_t)blockIdx.z * DM * DM;
    const float* bb; float* Y;
    if (blockIdx.z == 0)      { bb = bq; Y = g_Q; }
    else if (blockIdx.z == 1) { bb = bk; Y = g_K; }
    else                      { bb = bv; Y = g_V; }
    gemm_mma_body<true, 8>(g_Xr, W, bb, Y, blockIdx.y * 128, blockIdx.x * 256, smg);
}

__global__ __launch_bounds__(256) void gemm_mma_one(
    const float* __restrict__ bias, float* __restrict__ Y)
{
    extern __shared__ float smg[];
    gemm_mma_body<false, 6>(g_C, g_Wr + (size_t)3 * DM * DM, bias, Y,
                            blockIdx.y * 128, blockIdx.x * 192, smg);
}

// ===========================================================================
// tf32 mma attention (unchanged best config: 256 threads, A/B regions,
// software-pipelined cp.async, 4 syncthreads/tile).
// softmax over HEAD axis (local per (n,m)). Q/K/V pre-rounded tf32.
// ===========================================================================
#define AQ_STR 772
#define SA_K 516
#define SA_V 520
#define SB_K 260
#define SB_V 264
#define RA_OFF 24704
#define RB_OFF (RA_OFF + 32*SA_V)
#define ZP_OFF (RB_OFF + 32*SB_V)
#define ZP_STR 34
#define ZP_GRP (32*ZP_STR)
#define ATTN_SMEM_FLOATS (ZP_OFF + 4*ZP_GRP)
#define ATTN_SMEM_BYTES (ATTN_SMEM_FLOATS*4)

template<int KSTR>
__device__ __forceinline__ void score_pass(
    const uint32_t* __restrict__ qa, const uint32_t* __restrict__ kb,
    float s[4][4])
{
#pragma unroll
    for (int kk = 0; kk < 8; ++kk) {
        uint32_t a[4];
        a[0] = qa[kk*8];
        a[1] = qa[kk*8 + 8*AQ_STR];
        a[2] = qa[kk*8 + 4];
        a[3] = qa[kk*8 + 4 + 8*AQ_STR];
#pragma unroll
        for (int j = 0; j < 4; ++j) {
            uint32_t bb[2];
            bb[0] = kb[kk*8 + j*8*KSTR];
            bb[1] = kb[kk*8 + 4 + j*8*KSTR];
            mma_tf32(s[j], a, bb);
        }
    }
}

template<int VSTR>
__device__ __forceinline__ void av_pass(
    const uint32_t* __restrict__ vb, const float wp[4][4],
    const float iz0[4][2], const float iz1[4][2],
    float op[8][4], int srcA, bool odd)
{
#pragma unroll
    for (int kk = 0; kk < 4; ++kk) {
        float v0 = __shfl_sync(0xffffffffu, wp[kk][0], srcA);
        float v1 = __shfl_sync(0xffffffffu, wp[kk][1], srcA);
        float v2 = __shfl_sync(0xffffffffu, wp[kk][2], srcA);
        float v3 = __shfl_sync(0xffffffffu, wp[kk][3], srcA);
        float u0 = __shfl_sync(0xffffffffu, wp[kk][0], srcA + 2);
        float u1 = __shfl_sync(0xffffffffu, wp[kk][1], srcA + 2);
        float u2 = __shfl_sync(0xffffffffu, wp[kk][2], srcA + 2);
        float u3 = __shfl_sync(0xffffffffu, wp[kk][3], srcA + 2);
        float w00 = odd ? v1 : v0;
        float w10 = odd ? v3 : v2;
        float w01 = odd ? u1 : u0;
        float w11 = odd ? u3 : u2;
        uint32_t a[4];
        a[0] = cvt_tf32(w00 * iz0[kk][0]);
        a[1] = cvt_tf32(w10 * iz1[kk][0]);
        a[2] = cvt_tf32(w01 * iz0[kk][1]);
        a[3] = cvt_tf32(w11 * iz1[kk][1]);
#pragma unroll
        for (int j = 0; j < 8; ++j) {
            uint32_t bb[2];
            bb[0] = vb[kk*8*VSTR + j*8];
            bb[1] = vb[(kk*8+4)*VSTR + j*8];
            mma_tf32(op[j], a, bb);
        }
    }
}

__global__ __launch_bounds__(256) void attn_mma_kernel()
{
    extern __shared__ float smf[];
    float* Qs    = smf;
    float* RA    = smf + RA_OFF;
    float* RB    = smf + RB_OFF;
    float* zpart = smf + ZP_OFF;

    const int b   = blockIdx.y;
    const int n0  = blockIdx.x * 32;
    const int t   = threadIdx.x;
    const int wid = t >> 5, lane = t & 31;
    const int grp = wid >> 1, nh = wid & 1;
    const int g   = lane >> 2, tig = lane & 3;
    const int nb  = nh * 16;

    const float* Qg = g_Q + (size_t)(b*SEQ + n0)*DM;
    const float* Kg = g_K + (size_t)b*SEQ*DM;
    const float* Vg = g_V + (size_t)b*SEQ*DM;

    const int srow = t >> 3;
    const int sc   = t & 7;

    const uint32_t qdst  = (uint32_t)__cvta_generic_to_shared(Qs + srow*AQ_STR + sc*4);
    const uint32_t kadst = (uint32_t)__cvta_generic_to_shared(RA + srow*SA_K + sc*4);
    const uint32_t kbdst = (uint32_t)__cvta_generic_to_shared(RB + srow*SB_K + sc*4);
    const uint32_t vadst = (uint32_t)__cvta_generic_to_shared(RA + srow*SA_V + sc*4);
    const uint32_t vbdst = (uint32_t)__cvta_generic_to_shared(RB + srow*SB_V + sc*4);

    {
        const float* qsrc = Qg + (size_t)srow * DM + sc * 4;
#pragma unroll
        for (int i = 0; i < 24; ++i)
            cp16(qdst + i*128, qsrc + i*32);
        CP_COMMIT();
        const float* ksrc = Kg + (size_t)srow * DM + sc * 4;
#pragma unroll
        for (int i = 0; i < 16; ++i)
            cp16(kadst + i*128, ksrc + i*32);
        CP_COMMIT();
    }

    float o[3][8][4];
#pragma unroll
    for (int p = 0; p < 3; ++p)
#pragma unroll
        for (int j = 0; j < 8; ++j)
#pragma unroll
            for (int q = 0; q < 4; ++q) o[p][j][q] = 0.f;

    const int srcA = 4*g + (tig >> 1);
    const bool odd = (tig & 1);

    for (int m0 = 0; m0 < SEQ; m0 += 32) {
        CP_WAIT0();
        __syncthreads();   // KA visible (Q too on first iter)

        {
            const float* ksrc = Kg + (size_t)(m0 + srow) * DM + 512 + sc * 4;
#pragma unroll
            for (int i = 0; i < 8; ++i)
                cp16(kbdst + i*128, ksrc + i*32);
            CP_COMMIT();
        }

        float w[3][4][4];
        float wsum[4][4];
#pragma unroll
        for (int j = 0; j < 4; ++j)
#pragma unroll
            for (int q = 0; q < 4; ++q) wsum[j][q] = 0.f;

#pragma unroll
        for (int p = 0; p < 2; ++p) {
            const int h = grp + 4*p;
            float s[4][4];
#pragma unroll
            for (int j = 0; j < 4; ++j)
#pragma unroll
                for (int q = 0; q < 4; ++q) s[j][q] = 0.f;
            score_pass<SA_K>(
                (const uint32_t*)(Qs + (nb+g)*AQ_STR + h*64 + tig),
                (const uint32_t*)(RA + g*SA_K + h*64 + tig), s);
#pragma unroll
            for (int j = 0; j < 4; ++j) {
                float e0 = __expf(s[j][0]*0.125f);
                float e1 = __expf(s[j][1]*0.125f);
                float e2 = __expf(s[j][2]*0.125f);
                float e3 = __expf(s[j][3]*0.125f);
                w[p][j][0]=e0; w[p][j][1]=e1; w[p][j][2]=e2; w[p][j][3]=e3;
                wsum[j][0]+=e0; wsum[j][1]+=e1; wsum[j][2]+=e2; wsum[j][3]+=e3;
            }
        }

        CP_WAIT0();
        __syncthreads();   // KB visible; A free for VA

        {
            const float* vsrc = Vg + (size_t)(m0 + srow) * DM + sc * 4;
#pragma unroll
            for (int i = 0; i < 16; ++i)
                cp16(vadst + i*128, vsrc + i*32);
            CP_COMMIT();
        }

        {
            float s[4][4];
#pragma unroll
            for (int j = 0; j < 4; ++j)
#pragma unroll
                for (int q = 0; q < 4; ++q) s[j][q] = 0.f;
            score_pass<SB_K>(
                (const uint32_t*)(Qs + (nb+g)*AQ_STR + (grp+8)*64 + tig),
                (const uint32_t*)(RB + g*SB_K + grp*64 + tig), s);
#pragma unroll
            for (int j = 0; j < 4; ++j) {
                float e0 = __expf(s[j][0]*0.125f);
                float e1 = __expf(s[j][1]*0.125f);
                float e2 = __expf(s[j][2]*0.125f);
                float e3 = __expf(s[j][3]*0.125f);
                w[2][j][0]=e0; w[2][j][1]=e1; w[2][j][2]=e2; w[2][j][3]=e3;
                wsum[j][0]+=e0; wsum[j][1]+=e1; wsum[j][2]+=e2; wsum[j][3]+=e3;
            }
        }

        {
            float* zp = zpart + grp*ZP_GRP + (nb+g)*ZP_STR + 2*tig;
#pragma unroll
            for (int j = 0; j < 4; ++j) {
                *(float2*)(zp + j*8)            = make_float2(wsum[j][0], wsum[j][1]);
                *(float2*)(zp + 8*ZP_STR + j*8) = make_float2(wsum[j][2], wsum[j][3]);
            }
        }

        CP_WAIT0();
        __syncthreads();   // VA visible; zpart complete; B free for VB

        {
            const float* vsrc = Vg + (size_t)(m0 + srow) * DM + 512 + sc * 4;
#pragma unroll
            for (int i = 0; i < 8; ++i)
                cp16(vbdst + i*128, vsrc + i*32);
            CP_COMMIT();
        }

        float iz0[4][2], iz1[4][2];
        {
            const float* zlo = zpart + (nb+g)*ZP_STR;
            const float* zhi = zpart + (nb+g+8)*ZP_STR;
#pragma unroll
            for (int kk = 0; kk < 4; ++kk) {
#pragma unroll
                for (int e = 0; e < 2; ++e) {
                    int cidx = kk*8 + tig + e*4;
                    float zl = zlo[cidx] + zlo[ZP_GRP+cidx] + zlo[2*ZP_GRP+cidx] + zlo[3*ZP_GRP+cidx];
                    float zh = zhi[cidx] + zhi[ZP_GRP+cidx] + zhi[2*ZP_GRP+cidx] + zhi[3*ZP_GRP+cidx];
                    iz0[kk][e] = __fdividef(1.f, zl);
                    iz1[kk][e] = __fdividef(1.f, zh);
                }
            }
        }

#pragma unroll
        for (int p = 0; p < 2; ++p) {
            const int h = grp + 4*p;
            av_pass<SA_V>((const uint32_t*)(RA + tig*SA_V + h*64 + g),
                          w[p], iz0, iz1, o[p], srcA, odd);
        }

        CP_WAIT0();
        __syncthreads();   // VB visible; A free for next KA

        {
            if (m0 + 32 < SEQ) {
                const float* ksrc = Kg + (size_t)(m0 + 32 + srow) * DM + sc * 4;
#pragma unroll
                for (int i = 0; i < 16; ++i)
                    cp16(kadst + i*128, ksrc + i*32);
            }
            CP_COMMIT();
        }

        av_pass<SB_V>((const uint32_t*)(RB + tig*SB_V + grp*64 + g),
                      w[2], iz0, iz1, o[2], srcA, odd);
    }

    // ---- writeback (rounded to tf32 for the O-projection GEMM)
#pragma unroll
    for (int p = 0; p < 3; ++p) {
        const int h = grp + 4*p;
        float* Cp = g_C + (size_t)(b*SEQ + n0 + nb + g)*DM + h*64 + 2*tig;
#pragma unroll
        for (int j = 0; j < 8; ++j) {
            float2 r0, r1;
            r0.x = __uint_as_float(cvt_tf32(o[p][j][0]));
            r0.y = __uint_as_float(cvt_tf32(o[p][j][1]));
            r1.x = __uint_as_float(cvt_tf32(o[p][j][2]));
            r1.y = __uint_as_float(cvt_tf32(o[p][j][3]));
            *(float2*)(Cp + j*8)        = r0;
            *(float2*)(Cp + 8*DM + j*8) = r1;
        }
    }
}

// ===========================================================================
extern "C" void kernel_launch(void* const* d_in, const int* in_sizes, int n_in,
                              void* d_out, int out_size)
{
    const float* x  = (const float*)d_in[0];
    const float* Wq = (const float*)d_in[1];
    const float* bq = (const float*)d_in[2];
    const float* Wk = (const float*)d_in[3];
    const float* bk = (const float*)d_in[4];
    const float* Wv = (const float*)d_in[5];
    const float* bv = (const float*)d_in[6];
    const float* Wo = (const float*)d_in[7];
    const float* bo = (const float*)d_in[8];
    float* out = (float*)d_out;

    cudaFuncSetAttribute(attn_mma_kernel,
                         cudaFuncAttributeMaxDynamicSharedMemorySize,
                         ATTN_SMEM_BYTES);
    cudaFuncSetAttribute(gemm_mma_qkv,
                         cudaFuncAttributeMaxDynamicSharedMemorySize,
                         QKV_SMEM_BYTES);
    cudaFuncSetAttribute(gemm_mma_one,
                         cudaFuncAttributeMaxDynamicSharedMemorySize,
                         ONE_SMEM_BYTES);

    preround_kernel<<<PRE_BLOCKS, 256>>>(
        (const float4*)x, (const float4*)Wq, (const float4*)Wk,
        (const float4*)Wv, (const float4*)Wo);

    dim3 g3(DM/256, MTOT/128, 3);   // (3, 64, 3)
    gemm_mma_qkv<<<g3, 256, QKV_SMEM_BYTES>>>(bq, bk, bv);

    attn_mma_kernel<<<dim3(SEQ/32, BATCH), 256, ATTN_SMEM_BYTES>>>();

    dim3 gg(DM/192, MTOT/128);      // (4, 64) = 256 CTAs
    gemm_mma_one<<<gg, 256, ONE_SMEM_BYTES>>>(bo, out);
}